// round 16
// baseline (speedup 1.0000x reference)
#include <cuda_runtime.h>
#include <cuda_fp16.h>
#include <math.h>
#include <cstdint>

#define N_NODES 100000
#define F_DIM   128
#define DEG     5
#define N_EDGES (N_NODES * DEG)
#define MIN_NORM 1e-15f
#define MAXNORM  0.996f

// ---------------- scratch ----------------------------------------------------
__device__ __align__(16) __half g_mxH[(size_t)N_NODES * F_DIM];   // x @ W^T, fp16
__device__ __align__(16) float g_u[N_NODES];
__device__ __align__(16) float g_v[N_NODES];
__device__ int   g_cnt[N_NODES];
__device__ __align__(16) float g_msq[F_DIM];
__device__ __align__(16) float g_wsq[F_DIM];
__device__ __align__(16) float g_xs2[F_DIM];
__device__ __align__(16) float g_alpha[F_DIM];
__device__ float g_sumsqE;
__device__ float g_anorm;

// pre-split W in bf16 hi/lo, per K-chunk smem image: [chunk][hi ATILEB | lo ATILEB]
#define ROWB   144                       // 72 bf16 per row
#define ATILEB (128 * ROWB)              // 18432
__device__ __align__(16) unsigned char g_Wc[2][2 * ATILEB];

// ---------------- math helpers ------------------------------------------------
__device__ __forceinline__ float clip1(float x) {
    return fminf(fmaxf(x, -1.0f + 1e-7f), 1.0f - 1e-7f);
}
__device__ __forceinline__ float artanh_c(float x) { return atanhf(clip1(x)); }
__device__ __forceinline__ float proj_logmap0_factor(float s, float mn) {
    float r  = fabsf(s) * mn;
    float pf = (r > MAXNORM) ? (MAXNORM / r) : 1.0f;
    float pn = fmaxf(r * pf, MIN_NORM);
    return s * pf * artanh_c(pn) / pn;
}
__device__ __forceinline__ float expmap0_proj_factor(float un) {
    un = fmaxf(un, MIN_NORM);
    float g  = tanhf(un) / un;
    float r  = fabsf(g) * un;
    float pf = (r > MAXNORM) ? (MAXNORM / r) : 1.0f;
    return g * pf;
}

__device__ __forceinline__ uint32_t smem_u32(const void* p) {
    uint32_t a;
    asm("{ .reg .u64 t; cvta.to.shared.u64 t, %1; cvt.u32.u64 %0, t; }" : "=r"(a) : "l"(p));
    return a;
}

#define CVTPK(r, f0, f1) asm("cvt.rn.bf16x2.f32 %0, %1, %2;" : "=r"(r) : "f"(f1), "f"(f0))

#define LDSM_X4(r0, r1, r2, r3, addr)                                            \
    asm volatile("ldmatrix.sync.aligned.m8n8.x4.shared.b16 {%0,%1,%2,%3}, [%4];" \
        : "=r"(r0), "=r"(r1), "=r"(r2), "=r"(r3) : "r"(addr))

#define MMA_BF16(cp, a0, a1, a2, a3, b0, b1)                                     \
    asm volatile("mma.sync.aligned.m16n8k16.row.col.f32.bf16.bf16.f32 "          \
        "{%0,%1,%2,%3}, {%4,%5,%6,%7}, {%8,%9}, {%0,%1,%2,%3};"                  \
        : "+f"((cp)[0]), "+f"((cp)[1]), "+f"((cp)[2]), "+f"((cp)[3])             \
        : "r"(a0), "r"(a1), "r"(a2), "r"(a3), "r"(b0), "r"(b1))

// split float2 -> bf16x2 hi + bf16x2 residual lo (fragment-ready packing)
__device__ __forceinline__ void cvt2(float2 f, uint32_t& hi, uint32_t& lo) {
    CVTPK(hi, f.x, f.y);
    float l0 = f.x - __uint_as_float(hi << 16);
    float l1 = f.y - __uint_as_float(hi & 0xffff0000u);
    CVTPK(lo, l0, l1);
}

__device__ __forceinline__ void conv8p(uint4* hip, uint4* lop, float4 a, float4 b) {
    uint32_t p0, p1, p2, p3, q0, q1, q2, q3;
    cvt2(make_float2(a.x, a.y), p0, q0);
    cvt2(make_float2(a.z, a.w), p1, q1);
    cvt2(make_float2(b.x, b.y), p2, q2);
    cvt2(make_float2(b.z, b.w), p3, q3);
    *hip = make_uint4(p0, p1, p2, p3);
    *lop = make_uint4(q0, q1, q2, q3);
}

// ---------------- K_nil: zero small accumulators --------------------------------
__global__ void k_nil() {
    if (threadIdx.x < 128) { g_msq[threadIdx.x] = 0.0f; g_wsq[threadIdx.x] = 0.0f; }
    if (threadIdx.x == 128) g_sumsqE = 0.0f;
}

// ---------------- K0: hist (int2, 2 edges/thread) + W prep merged ---------------
__global__ void k_ph(const int* __restrict__ dst, const float* __restrict__ W) {
    int t = blockIdx.x * blockDim.x + threadIdx.x;
    int e0 = t * 2;
    if (e0 + 1 < N_EDGES) {
        int2 d = ((const int2*)dst)[t];
        atomicAdd(&g_cnt[d.x], 1);
        atomicAdd(&g_cnt[d.y], 1);
    } else if (e0 < N_EDGES) {
        atomicAdd(&g_cnt[dst[e0]], 1);
    }
    if (blockIdx.x < 16) {
        int row  = blockIdx.x * 8 + (threadIdx.x >> 5);
        int lane = threadIdx.x & 31;
        float s2 = 0.0f;
        if (lane < 16) {
            const float* p = &W[row * 128 + lane * 8];
            float4 a = *(const float4*)p;
            float4 b = *(const float4*)(p + 4);
            s2 = a.x * a.x + a.y * a.y + a.z * a.z + a.w * a.w
               + b.x * b.x + b.y * b.y + b.z * b.z + b.w * b.w;
            int chunk = lane >> 3, g = lane & 7;
            uint32_t off = (uint32_t)row * ROWB + g * 16;
            conv8p((uint4*)(g_Wc[chunk] + off),
                   (uint4*)(g_Wc[chunk] + ATILEB + off), a, b);
        }
#pragma unroll
        for (int o = 8; o > 0; o >>= 1) s2 += __shfl_xor_sync(0xffffffffu, s2, o);
        if (lane == 0) g_xs2[row] = s2;
    }
}

// ---------------- K1: bf16 3-split GEMM, m32n32 warps, 3 CTAs/SM -----------------
#define SM_TOT (4 * ATILEB)              // 73728: [chunk0 hi|lo][chunk1 hi|lo]

__global__ __launch_bounds__(256, 3) void k_gemm_mma(const float* __restrict__ x) {
    extern __shared__ __align__(1024) char smem[];
    const uint32_t sbase = smem_u32(smem);
    const int tid  = threadIdx.x;
    const int wid  = tid >> 5;
    const int lane = tid & 31;
    const int base = blockIdx.x * 64;    // M=64 rows per block

    const int wm = wid & 1, wn = wid >> 1;   // 2 m-warps x 4 n-warps
    const int wbase = wm * 32, nbase = wn * 32;

    // load full pre-split W (both chunks, hi+lo) into smem: 73728 B
    {
        const uint4* s4 = (const uint4*)g_Wc;
        uint4* d4 = (uint4*)smem;
#pragma unroll
        for (int it = 0; it < 18; it++) d4[tid + it * 256] = s4[tid + it * 256];
    }
    __syncthreads();

    const uint32_t b_row = (uint32_t)(nbase + ((lane >> 4) << 3) + (lane & 7));
    const uint32_t b_off = b_row * ROWB + (((lane >> 3) & 1) ? 16u : 0u);

    const int r  = lane >> 2;
    const int tg = lane & 3;
    const float* rp[4];
    bool rv[4];
#pragma unroll
    for (int i = 0; i < 4; i++) {
        int row = base + wbase + r + i * 8;
        rv[i] = row < N_NODES;
        rp[i] = x + (size_t)row * 128 + tg * 2;
    }

    float c[2][4][4];
#pragma unroll
    for (int m = 0; m < 2; m++)
#pragma unroll
        for (int i = 0; i < 4; i++)
#pragma unroll
            for (int j = 0; j < 4; j++) c[m][i][j] = 0.0f;

    const float2 z2 = make_float2(0.f, 0.f);

#pragma unroll
    for (int kk = 0; kk < 8; kk++) {            // 8 k-steps of 16 cols
        const int chunk = kk >> 2;
        const int ks    = kk & 3;
        const uint32_t bh_base = sbase + chunk * (2 * ATILEB) + b_off;
        const uint32_t bl_base = bh_base + ATILEB;
        const int c0 = kk * 16;

        uint32_t ah[8], al[8];
        {
            float2 f0 = rv[0] ? *(const float2*)(rp[0] + c0)     : z2;
            float2 f1 = rv[1] ? *(const float2*)(rp[1] + c0)     : z2;
            float2 f2 = rv[0] ? *(const float2*)(rp[0] + c0 + 8) : z2;
            float2 f3 = rv[1] ? *(const float2*)(rp[1] + c0 + 8) : z2;
            float2 f4 = rv[2] ? *(const float2*)(rp[2] + c0)     : z2;
            float2 f5 = rv[3] ? *(const float2*)(rp[3] + c0)     : z2;
            float2 f6 = rv[2] ? *(const float2*)(rp[2] + c0 + 8) : z2;
            float2 f7 = rv[3] ? *(const float2*)(rp[3] + c0 + 8) : z2;
            cvt2(f0, ah[0], al[0]); cvt2(f1, ah[1], al[1]);
            cvt2(f2, ah[2], al[2]); cvt2(f3, ah[3], al[3]);
            cvt2(f4, ah[4], al[4]); cvt2(f5, ah[5], al[5]);
            cvt2(f6, ah[6], al[6]); cvt2(f7, ah[7], al[7]);
        }
#pragma unroll
        for (int jj = 0; jj < 2; jj++) {
            uint32_t boff = jj * (16 * ROWB) + ks * 32;
            uint32_t bh0, bh1, bh2, bh3, bl0, bl1, bl2, bl3;
            LDSM_X4(bh0, bh1, bh2, bh3, bh_base + boff);
            LDSM_X4(bl0, bl1, bl2, bl3, bl_base + boff);
            MMA_BF16(c[0][2 * jj],     ah[0], ah[1], ah[2], ah[3], bh0, bh1);
            MMA_BF16(c[0][2 * jj + 1], ah[0], ah[1], ah[2], ah[3], bh2, bh3);
            MMA_BF16(c[1][2 * jj],     ah[4], ah[5], ah[6], ah[7], bh0, bh1);
            MMA_BF16(c[1][2 * jj + 1], ah[4], ah[5], ah[6], ah[7], bh2, bh3);
            MMA_BF16(c[0][2 * jj],     ah[0], ah[1], ah[2], ah[3], bl0, bl1);
            MMA_BF16(c[0][2 * jj + 1], ah[0], ah[1], ah[2], ah[3], bl2, bl3);
            MMA_BF16(c[1][2 * jj],     ah[4], ah[5], ah[6], ah[7], bl0, bl1);
            MMA_BF16(c[1][2 * jj + 1], ah[4], ah[5], ah[6], ah[7], bl2, bl3);
            MMA_BF16(c[0][2 * jj],     al[0], al[1], al[2], al[3], bh0, bh1);
            MMA_BF16(c[0][2 * jj + 1], al[0], al[1], al[2], al[3], bh2, bh3);
            MMA_BF16(c[1][2 * jj],     al[4], al[5], al[6], al[7], bh0, bh1);
            MMA_BF16(c[1][2 * jj + 1], al[4], al[5], al[6], al[7], bh2, bh3);
        }
    }

    // --- epilogue: store mx (fp16) + per-feature column sums ---------------------
    int r0 = base + wbase + (lane >> 2);
    int rows[4] = {r0, r0 + 8, r0 + 16, r0 + 24};
    float cf[4];
    bool vv[4];
#pragma unroll
    for (int i = 0; i < 4; i++) {
        vv[i] = rows[i] < N_NODES;
        cf[i] = vv[i] ? (float)g_cnt[rows[i]] : 0.0f;
    }

    __syncthreads();
    float* red = (float*)smem;             // [8 warps][64]: 32 ssq + 32 wsq
    float* redw = red + wid * 64;

#pragma unroll
    for (int nt = 0; nt < 4; nt++) {
        int col = nbase + nt * 8 + (lane & 3) * 2;
        float va[8] = {c[0][nt][0], c[0][nt][1], c[0][nt][2], c[0][nt][3],
                       c[1][nt][0], c[1][nt][1], c[1][nt][2], c[1][nt][3]};
        if (vv[0]) *(__half2*)&g_mxH[(size_t)rows[0] * 128 + col] = __floats2half2_rn(va[0], va[1]);
        if (vv[1]) *(__half2*)&g_mxH[(size_t)rows[1] * 128 + col] = __floats2half2_rn(va[2], va[3]);
        if (vv[2]) *(__half2*)&g_mxH[(size_t)rows[2] * 128 + col] = __floats2half2_rn(va[4], va[5]);
        if (vv[3]) *(__half2*)&g_mxH[(size_t)rows[3] * 128 + col] = __floats2half2_rn(va[6], va[7]);
        float s0 = 0.f, s1 = 0.f, w0 = 0.f, w1 = 0.f;
#pragma unroll
        for (int i = 0; i < 4; i++) {
            float q0 = va[2 * i] * va[2 * i], q1 = va[2 * i + 1] * va[2 * i + 1];
            s0 += q0; s1 += q1;
            w0 += cf[i] * q0; w1 += cf[i] * q1;
        }
#pragma unroll
        for (int o = 4; o <= 16; o <<= 1) {
            s0 += __shfl_xor_sync(0xffffffffu, s0, o);
            s1 += __shfl_xor_sync(0xffffffffu, s1, o);
            w0 += __shfl_xor_sync(0xffffffffu, w0, o);
            w1 += __shfl_xor_sync(0xffffffffu, w1, o);
        }
        if (lane < 4) {
            int lc = nt * 8 + lane * 2;
            redw[lc]          = s0;
            redw[lc + 1]      = s1;
            redw[32 + lc]     = w0;
            redw[32 + lc + 1] = w1;
        }
    }
    __syncthreads();

    {
        int col = tid & 127, arr = tid >> 7;
        int wnc = col >> 5, lc = (col & 31) + arr * 32;
        float s = red[(wnc * 2 + 0) * 64 + lc] + red[(wnc * 2 + 1) * 64 + lc];
        atomicAdd(arr ? &g_wsq[col] : &g_msq[col], s);
    }
}

// ---------------- K3: per-node dots (fp16, half-warp per node, prefetched) -----
__global__ __launch_bounds__(256) void k_uv(const float* __restrict__ a) {
    __shared__ float c1s[128], c2s[128];
    __shared__ float ared[8];
    const int tid = threadIdx.x, wid = tid >> 5, lane = tid & 31;

    float av = a[tid];
    float s = av * av;
#pragma unroll
    for (int o = 16; o > 0; o >>= 1) s += __shfl_xor_sync(0xffffffffu, s, o);
    if (lane == 0) ared[wid] = s;
    __syncthreads();

    if (tid < 128) {
        float an2 = ared[0] + ared[1] + ared[2] + ared[3]
                  + ared[4] + ared[5] + ared[6] + ared[7];
        float an = fmaxf(sqrtf(an2), MIN_NORM);
        int f = tid;
        float xn = fmaxf(sqrtf(g_xs2[f]), MIN_NORM);
        float mn = fmaxf(sqrtf(g_msq[f]), MIN_NORM);
        float s1 = tanhf(mn / xn * artanh_c(xn)) / mn;
        float alpha = proj_logmap0_factor(s1, mn);
        float un_s = fabsf(alpha) * sqrtf(5.0f * g_msq[f]);
        float un_d = fabsf(alpha) * sqrtf(g_wsq[f]);
        c1s[f] = a[f]       * expmap0_proj_factor(un_s) * alpha;
        c2s[f] = a[128 + f] * expmap0_proj_factor(un_d) * alpha;
        if (blockIdx.x == 0) {
            g_alpha[f] = alpha;
            if (f == 0) g_anorm = an;
        }
    }
    __syncthreads();

    const int hw = lane >> 4;            // half-warp id: 0/1
    const int hl = lane & 15;            // lane within half-warp
    float4 ca1 = *(const float4*)&c1s[hl * 8];
    float4 cb1 = *(const float4*)&c1s[hl * 8 + 4];
    float4 ca2 = *(const float4*)&c2s[hl * 8];
    float4 cb2 = *(const float4*)&c2s[hl * 8 + 4];

    const int nb = blockIdx.x * 64;
    uint4 hm[4];
    int   ns[4];
    bool  vl[4];
#pragma unroll
    for (int i = 0; i < 4; i++) {
        ns[i] = nb + i * 16 + wid * 2 + hw;
        vl[i] = ns[i] < N_NODES;
        if (vl[i]) hm[i] = *(const uint4*)&g_mxH[(size_t)ns[i] * 128 + hl * 8];
    }
#pragma unroll
    for (int i = 0; i < 4; i++) {
        if (vl[i]) {
            float2 m0 = __half22float2(*(__half2*)&hm[i].x);
            float2 m1 = __half22float2(*(__half2*)&hm[i].y);
            float2 m2 = __half22float2(*(__half2*)&hm[i].z);
            float2 m3 = __half22float2(*(__half2*)&hm[i].w);
            float du = m0.x * ca1.x + m0.y * ca1.y + m1.x * ca1.z + m1.y * ca1.w
                     + m2.x * cb1.x + m2.y * cb1.y + m3.x * cb1.z + m3.y * cb1.w;
            float dv = m0.x * ca2.x + m0.y * ca2.y + m1.x * ca2.z + m1.y * ca2.w
                     + m2.x * cb2.x + m2.y * cb2.y + m3.x * cb2.z + m3.y * cb2.w;
#pragma unroll
            for (int o = 8; o > 0; o >>= 1) {
                du += __shfl_xor_sync(0xffffffffu, du, o);
                dv += __shfl_xor_sync(0xffffffffu, dv, o);
            }
            if (hl == 0) { g_u[ns[i]] = du; g_v[ns[i]] = dv; }
        }
    }
}

// ---------------- K4: sum of squares of edge logits, 2 edges/thread -------------
__global__ __launch_bounds__(256) void k_sumsq(const int* __restrict__ dst) {
    __shared__ float sb[8];
    int t = blockIdx.x * 256 + threadIdx.x;
    float sq = 0.0f;
    int e0 = t * 2;
    if (e0 + 1 < N_EDGES) {
        int2 d = ((const int2*)dst)[t];
        float m0 = g_u[(e0    ) / 5] + g_v[d.x];
        float m1 = g_u[(e0 + 1) / 5] + g_v[d.y];
        sq = m0 * m0 + m1 * m1;
    } else if (e0 < N_EDGES) {
        float m = g_u[e0 / 5] + g_v[dst[e0]];
        sq = m * m;
    }
#pragma unroll
    for (int o = 16; o > 0; o >>= 1) sq += __shfl_xor_sync(0xffffffffu, sq, o);
    if ((threadIdx.x & 31) == 0) sb[threadIdx.x >> 5] = sq;
    __syncthreads();
    if (threadIdx.x == 0) {
        float ss = 0.0f;
#pragma unroll
        for (int w = 0; w < 8; w++) ss += sb[w];
        atomicAdd(&g_sumsqE, ss);
    }
}

// ---------------- K5: final aggregation, 4 nodes per warp -----------------------
__device__ __forceinline__ float compute_gamma() {
    float mn = fmaxf(sqrtf(g_sumsqE), MIN_NORM);
    float an = g_anorm;
    float s2 = tanhf(mn / an * artanh_c(an)) / mn;
    return proj_logmap0_factor(s2, mn);
}

__global__ __launch_bounds__(256) void k_final(const int* __restrict__ dst,
                                               float* __restrict__ out) {
    int gw   = (blockIdx.x * blockDim.x + threadIdx.x) >> 5;
    int lane = threadIdx.x & 31;
    int nb   = gw * 4;
    if (nb >= N_NODES) return;
    float gamma = compute_gamma();

    int grp = lane >> 3;
    int sub = lane & 7;
    int myn = nb + grp;
    float wj = 0.0f;
    int   dj = 0;
    if (sub < DEG && myn < N_NODES) {
        int e = myn * DEG + sub;
        dj = dst[e];
        float mxE = g_u[myn] + g_v[dj];
        float ee  = gamma * mxE;
        float ge  = 0.5f * ee * (1.0f + erff(ee * 0.70710678118654752f));
        wj = expf(-ge);
    }

    float4 acc[4];
    float wsum[4];
#pragma unroll
    for (int g = 0; g < 4; g++) { acc[g] = make_float4(0.f, 0.f, 0.f, 0.f); wsum[g] = 0.0f; }
    bool gv[4];
#pragma unroll
    for (int g = 0; g < 4; g++) gv[g] = (nb + g) < N_NODES;

#pragma unroll
    for (int j = 0; j < DEG; j++) {
#pragma unroll
        for (int g = 0; g < 4; g++) {
            float w = __shfl_sync(0xffffffffu, wj, g * 8 + j);
            int   d = __shfl_sync(0xffffffffu, dj, g * 8 + j);
            if (gv[g]) {
                uint2 hm = *(const uint2*)&g_mxH[(size_t)d * 128 + lane * 4];
                float2 m0 = __half22float2(*(__half2*)&hm.x);
                float2 m1 = __half22float2(*(__half2*)&hm.y);
                acc[g].x += w * m0.x; acc[g].y += w * m0.y;
                acc[g].z += w * m1.x; acc[g].w += w * m1.y;
                wsum[g] += w;
            }
        }
    }

    float4 al = *(const float4*)&g_alpha[lane * 4];

#pragma unroll
    for (int g = 0; g < 4; g++) {
        if (!gv[g]) continue;
        float inv = 1.0f / wsum[g];
        float4 hp = make_float4(acc[g].x * al.x * inv, acc[g].y * al.y * inv,
                                acc[g].z * al.z * inv, acc[g].w * al.w * inv);
        float4 e4;
        e4.x = (hp.x > 0.f) ? hp.x : expm1f(hp.x);
        e4.y = (hp.y > 0.f) ? hp.y : expm1f(hp.y);
        e4.z = (hp.z > 0.f) ? hp.z : expm1f(hp.z);
        e4.w = (hp.w > 0.f) ? hp.w : expm1f(hp.w);
        float ssq = e4.x * e4.x + e4.y * e4.y + e4.z * e4.z + e4.w * e4.w;
#pragma unroll
        for (int o = 16; o > 0; o >>= 1) ssq += __shfl_xor_sync(0xffffffffu, ssq, o);
        float un  = fmaxf(sqrtf(ssq), MIN_NORM);
        float fac = expmap0_proj_factor(un);
        *(float4*)&out[(size_t)(nb + g) * 128 + lane * 4] =
            make_float4(e4.x * fac, e4.y * fac, e4.z * fac, e4.w * fac);
    }
}

// ---------------- launch -----------------------------------------------------------
extern "C" void kernel_launch(void* const* d_in, const int* in_sizes, int n_in,
                              void* d_out, int out_size) {
    const float* x = nullptr;
    const float* W = nullptr;
    const float* a = nullptr;
    const int* edge = nullptr;
    for (int i = 0; i < n_in; i++) {
        switch (in_sizes[i]) {
            case N_NODES * F_DIM: x    = (const float*)d_in[i]; break;
            case 2 * N_EDGES:     edge = (const int*)d_in[i];   break;
            case F_DIM * F_DIM:   W    = (const float*)d_in[i]; break;
            case 2 * F_DIM:       a    = (const float*)d_in[i]; break;
            default: break;
        }
    }
    const int* dst = edge + N_EDGES;
    float* out = (float*)d_out;

    cudaFuncSetAttribute(k_gemm_mma, cudaFuncAttributeMaxDynamicSharedMemorySize, SM_TOT);

    void* cnt_ptr = nullptr;
    cudaGetSymbolAddress(&cnt_ptr, g_cnt);
    cudaMemsetAsync(cnt_ptr, 0, N_NODES * sizeof(int));

    k_nil<<<1, 256>>>();
    k_ph<<<(N_EDGES / 2 + 255) / 256, 256>>>(dst, W);
    k_gemm_mma<<<(N_NODES + 63) / 64, 256, SM_TOT>>>(x);
    k_uv<<<(N_NODES + 63) / 64, 256>>>(a);
    k_sumsq<<<(N_EDGES / 2 + 255) / 256, 256>>>(dst);
    k_final<<<(N_NODES + 31) / 32, 256>>>(dst, out);
    (void)out_size;
}

// round 17
// speedup vs baseline: 1.1169x; 1.1169x over previous
#include <cuda_runtime.h>
#include <cuda_fp16.h>
#include <math.h>
#include <cstdint>

#define N_NODES 100000
#define F_DIM   128
#define DEG     5
#define N_EDGES (N_NODES * DEG)
#define MIN_NORM 1e-15f
#define MAXNORM  0.996f
#define N_TILES ((N_NODES + 127) / 128)   // 782
#define G_GRID  296                        // 2 CTAs/SM * 148 SMs

// ---------------- scratch ----------------------------------------------------
__device__ __align__(16) __half g_mxH[(size_t)N_NODES * F_DIM];   // x @ W^T, fp16
__device__ __align__(16) float g_u[N_NODES];
__device__ __align__(16) float g_v[N_NODES];
__device__ int   g_cnt[N_NODES];
__device__ __align__(16) float g_msq[F_DIM];
__device__ __align__(16) float g_wsq[F_DIM];
__device__ __align__(16) float g_xs2[F_DIM];
__device__ __align__(16) float g_alpha[F_DIM];
__device__ float g_sumsqE;
__device__ float g_anorm;

// pre-split W in bf16 hi/lo, per K-chunk smem image: [chunk][hi ATILEB | lo ATILEB]
#define ROWB   144                       // 72 bf16 per row
#define ATILEB (128 * ROWB)              // 18432
__device__ __align__(16) unsigned char g_Wc[2][2 * ATILEB];

// ---------------- math helpers ------------------------------------------------
__device__ __forceinline__ float clip1(float x) {
    return fminf(fmaxf(x, -1.0f + 1e-7f), 1.0f - 1e-7f);
}
__device__ __forceinline__ float artanh_c(float x) { return atanhf(clip1(x)); }
__device__ __forceinline__ float proj_logmap0_factor(float s, float mn) {
    float r  = fabsf(s) * mn;
    float pf = (r > MAXNORM) ? (MAXNORM / r) : 1.0f;
    float pn = fmaxf(r * pf, MIN_NORM);
    return s * pf * artanh_c(pn) / pn;
}
__device__ __forceinline__ float expmap0_proj_factor(float un) {
    un = fmaxf(un, MIN_NORM);
    float g  = tanhf(un) / un;
    float r  = fabsf(g) * un;
    float pf = (r > MAXNORM) ? (MAXNORM / r) : 1.0f;
    return g * pf;
}

__device__ __forceinline__ uint32_t smem_u32(const void* p) {
    uint32_t a;
    asm("{ .reg .u64 t; cvta.to.shared.u64 t, %1; cvt.u32.u64 %0, t; }" : "=r"(a) : "l"(p));
    return a;
}

#define CVTPK(r, f0, f1) asm("cvt.rn.bf16x2.f32 %0, %1, %2;" : "=r"(r) : "f"(f1), "f"(f0))

#define LDSM_X4(r0, r1, r2, r3, addr)                                            \
    asm volatile("ldmatrix.sync.aligned.m8n8.x4.shared.b16 {%0,%1,%2,%3}, [%4];" \
        : "=r"(r0), "=r"(r1), "=r"(r2), "=r"(r3) : "r"(addr))

#define MMA_BF16(cp, a0, a1, a2, a3, b0, b1)                                     \
    asm volatile("mma.sync.aligned.m16n8k16.row.col.f32.bf16.bf16.f32 "          \
        "{%0,%1,%2,%3}, {%4,%5,%6,%7}, {%8,%9}, {%0,%1,%2,%3};"                  \
        : "+f"((cp)[0]), "+f"((cp)[1]), "+f"((cp)[2]), "+f"((cp)[3])             \
        : "r"(a0), "r"(a1), "r"(a2), "r"(a3), "r"(b0), "r"(b1))

// split float2 -> bf16x2 hi + bf16x2 residual lo (fragment-ready packing)
__device__ __forceinline__ void cvt2(float2 f, uint32_t& hi, uint32_t& lo) {
    CVTPK(hi, f.x, f.y);
    float l0 = f.x - __uint_as_float(hi << 16);
    float l1 = f.y - __uint_as_float(hi & 0xffff0000u);
    CVTPK(lo, l0, l1);
}

__device__ __forceinline__ void conv8p(uint4* hip, uint4* lop, float4 a, float4 b) {
    uint32_t p0, p1, p2, p3, q0, q1, q2, q3;
    cvt2(make_float2(a.x, a.y), p0, q0);
    cvt2(make_float2(a.z, a.w), p1, q1);
    cvt2(make_float2(b.x, b.y), p2, q2);
    cvt2(make_float2(b.z, b.w), p3, q3);
    *hip = make_uint4(p0, p1, p2, p3);
    *lop = make_uint4(q0, q1, q2, q3);
}

// ---------------- K0: hist (int2, 2 edges/thread) + W prep + zeroing ------------
// g_cnt is zeroed by a cudaMemsetAsync before this kernel.
__global__ void k_ph(const int* __restrict__ dst, const float* __restrict__ W) {
    int t = blockIdx.x * blockDim.x + threadIdx.x;
    int e0 = t * 2;
    if (e0 + 1 < N_EDGES) {
        int2 d = ((const int2*)dst)[t];
        atomicAdd(&g_cnt[d.x], 1);
        atomicAdd(&g_cnt[d.y], 1);
    } else if (e0 < N_EDGES) {
        atomicAdd(&g_cnt[dst[e0]], 1);
    }
    if (blockIdx.x < 16) {
        if (blockIdx.x == 0 && threadIdx.x < 129) {
            if (threadIdx.x < 128) { g_msq[threadIdx.x] = 0.0f; g_wsq[threadIdx.x] = 0.0f; }
            else g_sumsqE = 0.0f;
        }
        int row  = blockIdx.x * 8 + (threadIdx.x >> 5);
        int lane = threadIdx.x & 31;
        float s2 = 0.0f;
        if (lane < 16) {
            const float* p = &W[row * 128 + lane * 8];
            float4 a = *(const float4*)p;
            float4 b = *(const float4*)(p + 4);
            s2 = a.x * a.x + a.y * a.y + a.z * a.z + a.w * a.w
               + b.x * b.x + b.y * b.y + b.z * b.z + b.w * b.w;
            int chunk = lane >> 3, g = lane & 7;
            uint32_t off = (uint32_t)row * ROWB + g * 16;
            conv8p((uint4*)(g_Wc[chunk] + off),
                   (uint4*)(g_Wc[chunk] + ATILEB + off), a, b);
        }
#pragma unroll
        for (int o = 8; o > 0; o >>= 1) s2 += __shfl_xor_sync(0xffffffffu, s2, o);
        if (lane == 0) g_xs2[row] = s2;
    }
}

// ---------------- K1: persistent bf16 3-split GEMM, W resident ------------------
#define SM_RED (4 * ATILEB)              // reduction buffer after W tiles
#define SM_TOT (4 * ATILEB + 4096)       // 77824

__global__ __launch_bounds__(256, 2) void k_gemm_mma(const float* __restrict__ x) {
    extern __shared__ __align__(1024) char smem[];
    const uint32_t sbase = smem_u32(smem);
    const int tid  = threadIdx.x;
    const int wid  = tid >> 5;
    const int lane = tid & 31;

    const int wm = wid & 3, wn = wid >> 2;
    const int wbase = wm * 32, nbase = wn * 64;

    // load full pre-split W once (both chunks, hi+lo): 73728 B
    {
        const uint4* s4 = (const uint4*)g_Wc;
        uint4* d4 = (uint4*)smem;
#pragma unroll
        for (int it = 0; it < 18; it++) d4[tid + it * 256] = s4[tid + it * 256];
    }
    __syncthreads();

    const uint32_t b_row = (uint32_t)(nbase + ((lane >> 4) << 3) + (lane & 7));
    const uint32_t b_off = b_row * ROWB + (((lane >> 3) & 1) ? 16u : 0u);
    const int r  = lane >> 2;
    const int tg = lane & 3;
    float* red = (float*)(smem + SM_RED);      // [8 warps][128]
    float* redw = red + wid * 128;
    const float2 z2 = make_float2(0.f, 0.f);

    for (int tile = blockIdx.x; tile < N_TILES; tile += gridDim.x) {
        const int base = tile * 128;

        const float* rp[4];
        bool rv[4];
#pragma unroll
        for (int i = 0; i < 4; i++) {
            int row = base + wbase + r + i * 8;
            rv[i] = row < N_NODES;
            rp[i] = x + (size_t)row * 128 + tg * 2;
        }

        float c[2][8][4];
#pragma unroll
        for (int m = 0; m < 2; m++)
#pragma unroll
            for (int i = 0; i < 8; i++)
#pragma unroll
                for (int j = 0; j < 4; j++) c[m][i][j] = 0.0f;

#pragma unroll
        for (int kk = 0; kk < 8; kk++) {            // 8 k-steps of 16 cols
            const int chunk = kk >> 2;
            const int ks    = kk & 3;
            const uint32_t bh_base = sbase + chunk * (2 * ATILEB) + b_off;
            const uint32_t bl_base = bh_base + ATILEB;
            const int c0 = kk * 16;

            uint32_t ah[8], al[8];
            {
                float2 f0 = rv[0] ? *(const float2*)(rp[0] + c0)     : z2;
                float2 f1 = rv[1] ? *(const float2*)(rp[1] + c0)     : z2;
                float2 f2 = rv[0] ? *(const float2*)(rp[0] + c0 + 8) : z2;
                float2 f3 = rv[1] ? *(const float2*)(rp[1] + c0 + 8) : z2;
                float2 f4 = rv[2] ? *(const float2*)(rp[2] + c0)     : z2;
                float2 f5 = rv[3] ? *(const float2*)(rp[3] + c0)     : z2;
                float2 f6 = rv[2] ? *(const float2*)(rp[2] + c0 + 8) : z2;
                float2 f7 = rv[3] ? *(const float2*)(rp[3] + c0 + 8) : z2;
                cvt2(f0, ah[0], al[0]); cvt2(f1, ah[1], al[1]);
                cvt2(f2, ah[2], al[2]); cvt2(f3, ah[3], al[3]);
                cvt2(f4, ah[4], al[4]); cvt2(f5, ah[5], al[5]);
                cvt2(f6, ah[6], al[6]); cvt2(f7, ah[7], al[7]);
            }
#pragma unroll
            for (int jj = 0; jj < 4; jj++) {
                uint32_t boff = jj * (16 * ROWB) + ks * 32;
                uint32_t bh0, bh1, bh2, bh3, bl0, bl1, bl2, bl3;
                LDSM_X4(bh0, bh1, bh2, bh3, bh_base + boff);
                LDSM_X4(bl0, bl1, bl2, bl3, bl_base + boff);
                MMA_BF16(c[0][2 * jj],     ah[0], ah[1], ah[2], ah[3], bh0, bh1);
                MMA_BF16(c[0][2 * jj + 1], ah[0], ah[1], ah[2], ah[3], bh2, bh3);
                MMA_BF16(c[1][2 * jj],     ah[4], ah[5], ah[6], ah[7], bh0, bh1);
                MMA_BF16(c[1][2 * jj + 1], ah[4], ah[5], ah[6], ah[7], bh2, bh3);
                MMA_BF16(c[0][2 * jj],     ah[0], ah[1], ah[2], ah[3], bl0, bl1);
                MMA_BF16(c[0][2 * jj + 1], ah[0], ah[1], ah[2], ah[3], bl2, bl3);
                MMA_BF16(c[1][2 * jj],     ah[4], ah[5], ah[6], ah[7], bl0, bl1);
                MMA_BF16(c[1][2 * jj + 1], ah[4], ah[5], ah[6], ah[7], bl2, bl3);
                MMA_BF16(c[0][2 * jj],     al[0], al[1], al[2], al[3], bh0, bh1);
                MMA_BF16(c[0][2 * jj + 1], al[0], al[1], al[2], al[3], bh2, bh3);
                MMA_BF16(c[1][2 * jj],     al[4], al[5], al[6], al[7], bh0, bh1);
                MMA_BF16(c[1][2 * jj + 1], al[4], al[5], al[6], al[7], bh2, bh3);
            }
        }

        // --- epilogue: store mx (fp16) + per-feature column sums -----------------
        int r0 = base + wbase + (lane >> 2);
        int rows[4] = {r0, r0 + 8, r0 + 16, r0 + 24};
        float cf[4];
        bool vv[4];
#pragma unroll
        for (int i = 0; i < 4; i++) {
            vv[i] = rows[i] < N_NODES;
            cf[i] = vv[i] ? (float)g_cnt[rows[i]] : 0.0f;
        }

#pragma unroll
        for (int nt = 0; nt < 8; nt++) {
            int col = nbase + nt * 8 + (lane & 3) * 2;
            float va[8] = {c[0][nt][0], c[0][nt][1], c[0][nt][2], c[0][nt][3],
                           c[1][nt][0], c[1][nt][1], c[1][nt][2], c[1][nt][3]};
            if (vv[0]) *(__half2*)&g_mxH[(size_t)rows[0] * 128 + col] = __floats2half2_rn(va[0], va[1]);
            if (vv[1]) *(__half2*)&g_mxH[(size_t)rows[1] * 128 + col] = __floats2half2_rn(va[2], va[3]);
            if (vv[2]) *(__half2*)&g_mxH[(size_t)rows[2] * 128 + col] = __floats2half2_rn(va[4], va[5]);
            if (vv[3]) *(__half2*)&g_mxH[(size_t)rows[3] * 128 + col] = __floats2half2_rn(va[6], va[7]);
            float s0 = 0.f, s1 = 0.f, w0 = 0.f, w1 = 0.f;
#pragma unroll
            for (int i = 0; i < 4; i++) {
                float q0 = va[2 * i] * va[2 * i], q1 = va[2 * i + 1] * va[2 * i + 1];
                s0 += q0; s1 += q1;
                w0 += cf[i] * q0; w1 += cf[i] * q1;
            }
#pragma unroll
            for (int o = 4; o <= 16; o <<= 1) {
                s0 += __shfl_xor_sync(0xffffffffu, s0, o);
                s1 += __shfl_xor_sync(0xffffffffu, s1, o);
                w0 += __shfl_xor_sync(0xffffffffu, w0, o);
                w1 += __shfl_xor_sync(0xffffffffu, w1, o);
            }
            if (lane < 4) {
                int lc = nt * 8 + lane * 2;
                redw[lc]          = s0;
                redw[lc + 1]      = s1;
                redw[64 + lc]     = w0;
                redw[64 + lc + 1] = w1;
            }
        }
        __syncthreads();
        {
            int col = tid & 127, arr = tid >> 7;
            int wnc = col >> 6, lc = (col & 63) + arr * 64;
            float s = 0.0f;
#pragma unroll
            for (int wmc = 0; wmc < 4; wmc++) s += red[(wnc * 4 + wmc) * 128 + lc];
            atomicAdd(arr ? &g_wsq[col] : &g_msq[col], s);
        }
        __syncthreads();   // red consumed; safe for next tile
    }
}

// ---------------- K3: per-node dots (fp16, half-warp per node, prefetched) -----
__global__ __launch_bounds__(256) void k_uv(const float* __restrict__ a) {
    __shared__ float c1s[128], c2s[128];
    __shared__ float ared[8];
    const int tid = threadIdx.x, wid = tid >> 5, lane = tid & 31;

    float av = a[tid];
    float s = av * av;
#pragma unroll
    for (int o = 16; o > 0; o >>= 1) s += __shfl_xor_sync(0xffffffffu, s, o);
    if (lane == 0) ared[wid] = s;
    __syncthreads();

    if (tid < 128) {
        float an2 = ared[0] + ared[1] + ared[2] + ared[3]
                  + ared[4] + ared[5] + ared[6] + ared[7];
        float an = fmaxf(sqrtf(an2), MIN_NORM);
        int f = tid;
        float xn = fmaxf(sqrtf(g_xs2[f]), MIN_NORM);
        float mn = fmaxf(sqrtf(g_msq[f]), MIN_NORM);
        float s1 = tanhf(mn / xn * artanh_c(xn)) / mn;
        float alpha = proj_logmap0_factor(s1, mn);
        float un_s = fabsf(alpha) * sqrtf(5.0f * g_msq[f]);
        float un_d = fabsf(alpha) * sqrtf(g_wsq[f]);
        c1s[f] = a[f]       * expmap0_proj_factor(un_s) * alpha;
        c2s[f] = a[128 + f] * expmap0_proj_factor(un_d) * alpha;
        if (blockIdx.x == 0) {
            g_alpha[f] = alpha;
            if (f == 0) g_anorm = an;
        }
    }
    __syncthreads();

    const int hw = lane >> 4;
    const int hl = lane & 15;
    float4 ca1 = *(const float4*)&c1s[hl * 8];
    float4 cb1 = *(const float4*)&c1s[hl * 8 + 4];
    float4 ca2 = *(const float4*)&c2s[hl * 8];
    float4 cb2 = *(const float4*)&c2s[hl * 8 + 4];

    const int nb = blockIdx.x * 64;
    uint4 hm[4];
    int   ns[4];
    bool  vl[4];
#pragma unroll
    for (int i = 0; i < 4; i++) {
        ns[i] = nb + i * 16 + wid * 2 + hw;
        vl[i] = ns[i] < N_NODES;
        if (vl[i]) hm[i] = *(const uint4*)&g_mxH[(size_t)ns[i] * 128 + hl * 8];
    }
#pragma unroll
    for (int i = 0; i < 4; i++) {
        if (vl[i]) {
            float2 m0 = __half22float2(*(__half2*)&hm[i].x);
            float2 m1 = __half22float2(*(__half2*)&hm[i].y);
            float2 m2 = __half22float2(*(__half2*)&hm[i].z);
            float2 m3 = __half22float2(*(__half2*)&hm[i].w);
            float du = m0.x * ca1.x + m0.y * ca1.y + m1.x * ca1.z + m1.y * ca1.w
                     + m2.x * cb1.x + m2.y * cb1.y + m3.x * cb1.z + m3.y * cb1.w;
            float dv = m0.x * ca2.x + m0.y * ca2.y + m1.x * ca2.z + m1.y * ca2.w
                     + m2.x * cb2.x + m2.y * cb2.y + m3.x * cb2.z + m3.y * cb2.w;
#pragma unroll
            for (int o = 8; o > 0; o >>= 1) {
                du += __shfl_xor_sync(0xffffffffu, du, o);
                dv += __shfl_xor_sync(0xffffffffu, dv, o);
            }
            if (hl == 0) { g_u[ns[i]] = du; g_v[ns[i]] = dv; }
        }
    }
}

// ---------------- K4: sum of squares of edge logits, 2 edges/thread -------------
__global__ __launch_bounds__(256) void k_sumsq(const int* __restrict__ dst) {
    __shared__ float sb[8];
    int t = blockIdx.x * 256 + threadIdx.x;
    float sq = 0.0f;
    int e0 = t * 2;
    if (e0 + 1 < N_EDGES) {
        int2 d = ((const int2*)dst)[t];
        float m0 = g_u[(e0    ) / 5] + g_v[d.x];
        float m1 = g_u[(e0 + 1) / 5] + g_v[d.y];
        sq = m0 * m0 + m1 * m1;
    } else if (e0 < N_EDGES) {
        float m = g_u[e0 / 5] + g_v[dst[e0]];
        sq = m * m;
    }
#pragma unroll
    for (int o = 16; o > 0; o >>= 1) sq += __shfl_xor_sync(0xffffffffu, sq, o);
    if ((threadIdx.x & 31) == 0) sb[threadIdx.x >> 5] = sq;
    __syncthreads();
    if (threadIdx.x == 0) {
        float ss = 0.0f;
#pragma unroll
        for (int w = 0; w < 8; w++) ss += sb[w];
        atomicAdd(&g_sumsqE, ss);
    }
}

// ---------------- K5: final aggregation, 4 nodes per warp -----------------------
__device__ __forceinline__ float compute_gamma() {
    float mn = fmaxf(sqrtf(g_sumsqE), MIN_NORM);
    float an = g_anorm;
    float s2 = tanhf(mn / an * artanh_c(an)) / mn;
    return proj_logmap0_factor(s2, mn);
}

__global__ __launch_bounds__(256) void k_final(const int* __restrict__ dst,
                                               float* __restrict__ out) {
    int gw   = (blockIdx.x * blockDim.x + threadIdx.x) >> 5;
    int lane = threadIdx.x & 31;
    int nb   = gw * 4;
    if (nb >= N_NODES) return;
    float gamma = compute_gamma();

    int grp = lane >> 3;
    int sub = lane & 7;
    int myn = nb + grp;
    float wj = 0.0f;
    int   dj = 0;
    if (sub < DEG && myn < N_NODES) {
        int e = myn * DEG + sub;
        dj = dst[e];
        float mxE = g_u[myn] + g_v[dj];
        float ee  = gamma * mxE;
        float ge  = 0.5f * ee * (1.0f + erff(ee * 0.70710678118654752f));
        wj = expf(-ge);
    }

    float4 acc[4];
    float wsum[4];
#pragma unroll
    for (int g = 0; g < 4; g++) { acc[g] = make_float4(0.f, 0.f, 0.f, 0.f); wsum[g] = 0.0f; }
    bool gv[4];
#pragma unroll
    for (int g = 0; g < 4; g++) gv[g] = (nb + g) < N_NODES;

#pragma unroll
    for (int j = 0; j < DEG; j++) {
#pragma unroll
        for (int g = 0; g < 4; g++) {
            float w = __shfl_sync(0xffffffffu, wj, g * 8 + j);
            int   d = __shfl_sync(0xffffffffu, dj, g * 8 + j);
            if (gv[g]) {
                uint2 hm = *(const uint2*)&g_mxH[(size_t)d * 128 + lane * 4];
                float2 m0 = __half22float2(*(__half2*)&hm.x);
                float2 m1 = __half22float2(*(__half2*)&hm.y);
                acc[g].x += w * m0.x; acc[g].y += w * m0.y;
                acc[g].z += w * m1.x; acc[g].w += w * m1.y;
                wsum[g] += w;
            }
        }
    }

    float4 al = *(const float4*)&g_alpha[lane * 4];

#pragma unroll
    for (int g = 0; g < 4; g++) {
        if (!gv[g]) continue;
        float inv = 1.0f / wsum[g];
        float4 hp = make_float4(acc[g].x * al.x * inv, acc[g].y * al.y * inv,
                                acc[g].z * al.z * inv, acc[g].w * al.w * inv);
        float4 e4;
        e4.x = (hp.x > 0.f) ? hp.x : expm1f(hp.x);
        e4.y = (hp.y > 0.f) ? hp.y : expm1f(hp.y);
        e4.z = (hp.z > 0.f) ? hp.z : expm1f(hp.z);
        e4.w = (hp.w > 0.f) ? hp.w : expm1f(hp.w);
        float ssq = e4.x * e4.x + e4.y * e4.y + e4.z * e4.z + e4.w * e4.w;
#pragma unroll
        for (int o = 16; o > 0; o >>= 1) ssq += __shfl_xor_sync(0xffffffffu, ssq, o);
        float un  = fmaxf(sqrtf(ssq), MIN_NORM);
        float fac = expmap0_proj_factor(un);
        *(float4*)&out[(size_t)(nb + g) * 128 + lane * 4] =
            make_float4(e4.x * fac, e4.y * fac, e4.z * fac, e4.w * fac);
    }
}

// ---------------- launch -----------------------------------------------------------
extern "C" void kernel_launch(void* const* d_in, const int* in_sizes, int n_in,
                              void* d_out, int out_size) {
    const float* x = nullptr;
    const float* W = nullptr;
    const float* a = nullptr;
    const int* edge = nullptr;
    for (int i = 0; i < n_in; i++) {
        switch (in_sizes[i]) {
            case N_NODES * F_DIM: x    = (const float*)d_in[i]; break;
            case 2 * N_EDGES:     edge = (const int*)d_in[i];   break;
            case F_DIM * F_DIM:   W    = (const float*)d_in[i]; break;
            case 2 * F_DIM:       a    = (const float*)d_in[i]; break;
            default: break;
        }
    }
    const int* dst = edge + N_EDGES;
    float* out = (float*)d_out;

    cudaFuncSetAttribute(k_gemm_mma, cudaFuncAttributeMaxDynamicSharedMemorySize, SM_TOT);

    void* cnt_ptr = nullptr;
    cudaGetSymbolAddress(&cnt_ptr, g_cnt);
    cudaMemsetAsync(cnt_ptr, 0, N_NODES * sizeof(int));

    k_ph<<<(N_EDGES / 2 + 255) / 256, 256>>>(dst, W);
    k_gemm_mma<<<G_GRID, 256, SM_TOT>>>(x);
    k_uv<<<(N_NODES + 63) / 64, 256>>>(a);
    k_sumsq<<<(N_EDGES / 2 + 255) / 256, 256>>>(dst);
    k_final<<<(N_NODES + 31) / 32, 256>>>(dst, out);
    (void)out_size;
}